// round 8
// baseline (speedup 1.0000x reference)
#include <cuda_runtime.h>
#include <math.h>

// Problem constants: B=32, T=512, D=H=512, L=2
// Inputs (metadata order): x, Wr, br, Wu, bu, Wo, bo
// Output: (L, B, H) float32 = 32768 elements.

#define T_LEN 512
#define BATCH 32
#define HID   512

// ---------------- device scratch (no cudaMalloc allowed) ----------------
__device__ float    g_XP[(size_t)16384 * 1536];   // x-projections [m=t*32+b][n=g*512+j], g:0=u,1=r,2=o
__device__ float    g_Hseq[(size_t)16384 * 512];  // layer-0 hidden sequence [m=t*32+b][j]
__device__ float    g_hbuf[2][BATCH * HID];       // ping-pong h, [b][j]
__device__ float    g_hr[BATCH * HID];            // h*r exchange, [b][j]
__device__ unsigned g_bar[4];                     // per-batch-group barrier counters

__global__ void reset_kernel() {
    if (threadIdx.x < 4) g_bar[threadIdx.x] = 0u;
}

// ============================================================================
// xproj GEMM: g_XP[m][n] = A[m][0:512] . W_g[j][0:512] + b_g[j]
//   amode 0: A = x, row(m) = ((m&31)*T + (m>>5)) * D   (m = t*32+b, x is [B][T][D])
//   amode 1: A = g_Hseq, row(m) = m*512
// BM=BN=64, BK=16, 256 threads, 4x4 per thread.
// ============================================================================
__global__ __launch_bounds__(256) void xproj_kernel(
    const float* __restrict__ A, int amode,
    const float* __restrict__ Wr, const float* __restrict__ Wu, const float* __restrict__ Wo,
    const float* __restrict__ br, const float* __restrict__ bu, const float* __restrict__ bo)
{
    __shared__ float As[64][20];
    __shared__ float Bs[16][68];

    const float* Ap = amode ? (const float*)g_Hseq : A;
    int m0 = blockIdx.x * 64;
    int n0 = blockIdx.y * 64;
    int g  = n0 >> 9;            // gate uniform per block (BN=64 divides 512)
    int j0 = n0 & 511;
    const float* W  = (g == 0) ? Wu : (g == 1) ? Wr : Wo;
    const float* bv = (g == 0) ? bu : (g == 1) ? br : bo;

    int tid = threadIdx.x;
    int lr = tid >> 2;           // 0..63
    int lq = (tid & 3) * 4;      // 0,4,8,12

    size_t arow;
    {
        int m = m0 + lr;
        arow = amode ? (size_t)m * 512
                     : ((size_t)(m & 31) * 512 + (m >> 5)) * 512;
    }
    size_t wrow = (size_t)(j0 + lr) * 1024;

    int tx = tid & 15, ty = tid >> 4;
    float acc[4][4];
#pragma unroll
    for (int i = 0; i < 4; i++)
#pragma unroll
        for (int j = 0; j < 4; j++) acc[i][j] = 0.f;

    for (int k0 = 0; k0 < 512; k0 += 16) {
        float4 av = *(const float4*)(Ap + arow + k0 + lq);
        *(float4*)&As[lr][lq] = av;
        float4 wv = *(const float4*)(W + wrow + k0 + lq);
        Bs[lq + 0][lr] = wv.x; Bs[lq + 1][lr] = wv.y;
        Bs[lq + 2][lr] = wv.z; Bs[lq + 3][lr] = wv.w;
        __syncthreads();
#pragma unroll
        for (int kk = 0; kk < 16; kk++) {
            float a0 = As[ty * 4 + 0][kk];
            float a1 = As[ty * 4 + 1][kk];
            float a2 = As[ty * 4 + 2][kk];
            float a3 = As[ty * 4 + 3][kk];
            float4 b4 = *(const float4*)&Bs[kk][tx * 4];
            acc[0][0] = fmaf(a0, b4.x, acc[0][0]);
            acc[0][1] = fmaf(a0, b4.y, acc[0][1]);
            acc[0][2] = fmaf(a0, b4.z, acc[0][2]);
            acc[0][3] = fmaf(a0, b4.w, acc[0][3]);
            acc[1][0] = fmaf(a1, b4.x, acc[1][0]);
            acc[1][1] = fmaf(a1, b4.y, acc[1][1]);
            acc[1][2] = fmaf(a1, b4.z, acc[1][2]);
            acc[1][3] = fmaf(a1, b4.w, acc[1][3]);
            acc[2][0] = fmaf(a2, b4.x, acc[2][0]);
            acc[2][1] = fmaf(a2, b4.y, acc[2][1]);
            acc[2][2] = fmaf(a2, b4.z, acc[2][2]);
            acc[2][3] = fmaf(a2, b4.w, acc[2][3]);
            acc[3][0] = fmaf(a3, b4.x, acc[3][0]);
            acc[3][1] = fmaf(a3, b4.y, acc[3][1]);
            acc[3][2] = fmaf(a3, b4.z, acc[3][2]);
            acc[3][3] = fmaf(a3, b4.w, acc[3][3]);
        }
        __syncthreads();
    }

    float bb0 = bv[j0 + tx * 4 + 0];
    float bb1 = bv[j0 + tx * 4 + 1];
    float bb2 = bv[j0 + tx * 4 + 2];
    float bb3 = bv[j0 + tx * 4 + 3];
#pragma unroll
    for (int i = 0; i < 4; i++) {
        size_t m = (size_t)m0 + ty * 4 + i;
        float4 o;
        o.x = acc[i][0] + bb0;
        o.y = acc[i][1] + bb1;
        o.z = acc[i][2] + bb2;
        o.w = acc[i][3] + bb3;
        *(float4*)(g_XP + m * 1536 + n0 + tx * 4) = o;
    }
}

// ============================================================================
// Persistent scan kernel. 128 CTAs = 32 column-groups (16 j each) x 4 batch-
// groups (8 b each). Per-CTA SMEM: Wh slices for u/r/o (96 KB, resident all
// steps) + h / h*r staging + split-K reduction buffer. All cross-CTA traffic
// stays within a batch-group -> 4 independent 32-CTA barriers.
// ============================================================================

__device__ __forceinline__ void bg_barrier(int bg, unsigned target) {
    __syncthreads();
    if (threadIdx.x == 0) {
        __threadfence();                       // release my CTA's stores (gpu scope)
        atomicAdd(&g_bar[bg], 1u);
        while (((volatile unsigned*)g_bar)[bg] < target) { }
        __threadfence();                       // acquire side
    }
    __syncthreads();
}

__device__ __forceinline__ float4 ldvol4(const float* p) {
    float4 v;
    asm volatile("ld.volatile.global.v4.f32 {%0,%1,%2,%3}, [%4];"
                 : "=f"(v.x), "=f"(v.y), "=f"(v.z), "=f"(v.w)
                 : "l"(p) : "memory");
    return v;
}

// SMEM layout (floats): Wu_s[16*512] @0, Wr_s @8192, Wo_s @16384,
// h_s[8][516] @24576, hr_s[8][516] @28704, red[4352] @32832, U_s[16*8] @37184
#define SCAN_SMEM_FLOATS 37312
#define SCAN_SMEM_BYTES  (SCAN_SMEM_FLOATS * 4)

__global__ __launch_bounds__(256, 1) void scan_kernel(
    int layer,
    const float* __restrict__ Wr_l, const float* __restrict__ Wu_l,
    const float* __restrict__ Wo_l,
    float* __restrict__ dout)
{
    extern __shared__ float sm[];
    float* h_s  = sm + 24576;   // [8][516]
    float* hr_s = sm + 28704;   // [8][516]
    float* red  = sm + 32832;   // max(256*17, 128*33) = 4352
    float* U_s  = sm + 37184;   // [16][8]: jl*8 + b

    int tid = threadIdx.x;
    int cg = blockIdx.x >> 2;   // 0..31 column group (j in [cg*16, cg*16+16))
    int bg = blockIdx.x & 3;    // 0..3  batch group  (b in [bg*8,  bg*8+8))

    // Load recurrent-weight slices W_g[j][512:1024] -> SMEM (coalesced float4)
    {
        const float* srcs[3] = { Wu_l, Wr_l, Wo_l };
#pragma unroll
        for (int g = 0; g < 3; g++) {
            const float* src = srcs[g];
            float* dst = sm + g * 8192;
            for (int it = 0; it < 8; it++) {
                int word = (it * 256 + tid) * 4;
                int jl = word >> 9, k = word & 511;
                float4 v = *(const float4*)(src + (size_t)(cg * 16 + jl) * 1024 + 512 + k);
                *(float4*)(dst + jl * 512 + k) = v;
            }
        }
    }
    // zero own slice of h0
    if (tid < 128) {
        int b = tid >> 4, jl = tid & 15;
        g_hbuf[0][(bg * 8 + b) * 512 + cg * 16 + jl] = 0.f;
    }
    unsigned gen = 0;
    bg_barrier(bg, (++gen) * 32);

    // Phase-1 mapping: warp w = j-tile (4 (j,gate)-cols), lane: ks1 = lane&15
    // (split-K 16, stride-16 interleave), th = lane>>4 (b-tile of 4).
    // Phase-2 mapping: warp = (jt2, bt2) tile, lane = ks2 (split-K 32, stride-32).
    int w = tid >> 5, lane = tid & 31;
    int ks1 = lane & 15, th = lane >> 4;
    int jt2 = w >> 1, bt2 = w & 1, ks2 = lane;

    const float* Wp1 = (w < 4) ? (sm + (w * 4) * 512)
                               : (sm + 8192 + (w * 4 - 16) * 512);
    const float* Wp2 = sm + 16384 + (jt2 * 4) * 512;

    int cur = 0;
    for (int t = 0; t < 512; t++) {
        // ---- stage h (own 8 batches, full 512 cols) into SMEM ----
#pragma unroll
        for (int q = 0; q < 4; q++) {
            int f = (q * 256 + tid) * 4;
            int bl = f >> 9, k = f & 511;
            float4 v = ldvol4(&g_hbuf[cur][(bg * 8 + bl) * 512 + k]);
            *(float4*)(h_s + bl * 516 + k) = v;
        }
        __syncthreads();

        // ---- phase 1: u and r gates (32 (j,g)-cols x 8 b per CTA) ----
        float acc[4][4];
#pragma unroll
        for (int a = 0; a < 4; a++)
#pragma unroll
            for (int b = 0; b < 4; b++) acc[a][b] = 0.f;
        {
            const float* hp = h_s + (th * 4) * 516;
#pragma unroll 4
            for (int i = 0; i < 32; i++) {
                int k = ks1 + 16 * i;
                float h0 = hp[k], h1 = hp[516 + k], h2 = hp[1032 + k], h3 = hp[1548 + k];
#pragma unroll
                for (int ji = 0; ji < 4; ji++) {
                    float wv = Wp1[ji * 512 + k];
                    acc[ji][0] = fmaf(wv, h0, acc[ji][0]);
                    acc[ji][1] = fmaf(wv, h1, acc[ji][1]);
                    acc[ji][2] = fmaf(wv, h2, acc[ji][2]);
                    acc[ji][3] = fmaf(wv, h3, acc[ji][3]);
                }
            }
        }
#pragma unroll
        for (int ji = 0; ji < 4; ji++)
#pragma unroll
            for (int bi = 0; bi < 4; bi++)
                red[((w * 4 + ji) * 8 + th * 4 + bi) * 17 + ks1] = acc[ji][bi];
        __syncthreads();
        {
            int o = tid, jg = o >> 3, b = o & 7;
            float s = 0.f;
#pragma unroll
            for (int kk = 0; kk < 16; kk++) s += red[o * 17 + kk];
            size_t m = (size_t)t * 32 + bg * 8 + b;
            if (jg < 16) {                      // update gate u
                float pre = s + g_XP[m * 1536 + cg * 16 + jg];
                U_s[jg * 8 + b] = 1.f / (1.f + expf(-pre));
            } else {                            // reset gate r -> publish h*r
                int j = cg * 16 + (jg - 16);
                float pre = s + g_XP[m * 1536 + 512 + j];
                float r = 1.f / (1.f + expf(-pre));
                g_hr[(bg * 8 + b) * 512 + j] = h_s[b * 516 + j] * r;
            }
        }
        bg_barrier(bg, (++gen) * 32);

        // ---- phase 2: o gate + h update (16 j x 8 b per CTA) ----
#pragma unroll
        for (int q = 0; q < 4; q++) {
            int f = (q * 256 + tid) * 4;
            int bl = f >> 9, k = f & 511;
            float4 v = ldvol4(&g_hr[(bg * 8 + bl) * 512 + k]);
            *(float4*)(hr_s + bl * 516 + k) = v;
        }
        __syncthreads();
        float a2[4][4];
#pragma unroll
        for (int a = 0; a < 4; a++)
#pragma unroll
            for (int b = 0; b < 4; b++) a2[a][b] = 0.f;
        {
            const float* hp = hr_s + (bt2 * 4) * 516;
#pragma unroll 4
            for (int i = 0; i < 16; i++) {
                int k = ks2 + 32 * i;
                float h0 = hp[k], h1 = hp[516 + k], h2 = hp[1032 + k], h3 = hp[1548 + k];
#pragma unroll
                for (int ji = 0; ji < 4; ji++) {
                    float wv = Wp2[ji * 512 + k];
                    a2[ji][0] = fmaf(wv, h0, a2[ji][0]);
                    a2[ji][1] = fmaf(wv, h1, a2[ji][1]);
                    a2[ji][2] = fmaf(wv, h2, a2[ji][2]);
                    a2[ji][3] = fmaf(wv, h3, a2[ji][3]);
                }
            }
        }
#pragma unroll
        for (int ji = 0; ji < 4; ji++)
#pragma unroll
            for (int bi = 0; bi < 4; bi++)
                red[((jt2 * 4 + ji) * 8 + bt2 * 4 + bi) * 33 + ks2] = a2[ji][bi];
        __syncthreads();
        if (tid < 128) {
            int o = tid, jl = o >> 3, b = o & 7;
            float s = 0.f;
#pragma unroll
            for (int kk = 0; kk < 32; kk++) s += red[o * 33 + kk];
            int j = cg * 16 + jl;
            int bglob = bg * 8 + b;
            size_t m = (size_t)t * 32 + bglob;
            float pre = s + g_XP[m * 1536 + 1024 + j];
            float ov = tanhf(pre);
            float u = U_s[jl * 8 + b];
            float hold = h_s[b * 516 + j];
            float hn = fmaf(u, ov - hold, hold);      // h*(1-u) + o*u
            g_hbuf[cur ^ 1][bglob * 512 + j] = hn;
            if (layer == 0) g_Hseq[m * 512 + j] = hn;
            if (t == 511) dout[layer * 16384 + bglob * 512 + j] = hn;
        }
        bg_barrier(bg, (++gen) * 32);
        cur ^= 1;
    }
}

// ============================================================================
extern "C" void kernel_launch(void* const* d_in, const int* in_sizes, int n_in,
                              void* d_out, int out_size)
{
    (void)in_sizes; (void)n_in; (void)out_size;
    const float* x  = (const float*)d_in[0];
    const float* Wr = (const float*)d_in[1];
    const float* br = (const float*)d_in[2];
    const float* Wu = (const float*)d_in[3];
    const float* bu = (const float*)d_in[4];
    const float* Wo = (const float*)d_in[5];
    const float* bo = (const float*)d_in[6];
    float* out = (float*)d_out;

    cudaFuncSetAttribute(scan_kernel,
                         cudaFuncAttributeMaxDynamicSharedMemorySize,
                         SCAN_SMEM_BYTES);

    for (int l = 0; l < 2; l++) {
        size_t woff = (size_t)l * 512 * 1024;
        reset_kernel<<<1, 32>>>();
        xproj_kernel<<<dim3(256, 24), 256>>>(x, l,
                                             Wr + woff, Wu + woff, Wo + woff,
                                             br + l * 512, bu + l * 512, bo + l * 512);
        scan_kernel<<<128, 256, SCAN_SMEM_BYTES>>>(l,
                                                   Wr + woff, Wu + woff, Wo + woff,
                                                   out);
    }
}

// round 9
// speedup vs baseline: 1.1856x; 1.1856x over previous
#include <cuda_runtime.h>
#include <cuda_bf16.h>
#include <math.h>

// Problem constants: B=32, T=512, D=H=512, L=2
// Inputs (metadata order): x, Wr, br, Wu, bu, Wo, bo
// Output: (L, B, H) float32 = 32768 elements.

#define T_LEN 512
#define BATCH 32
#define HID   512

// ---------------- device scratch (no cudaMalloc allowed) ----------------
__device__ float    g_XP[(size_t)16384 * 1536];   // x-projections [m=t*32+b][n=g*512+j], g:0=u,1=r,2=o
__device__ float    g_Hseq[(size_t)16384 * 512];  // layer-0 hidden sequence [m=t*32+b][j]
__device__ float    g_hbuf[2][BATCH * HID];       // ping-pong h, [b][j]
__device__ float    g_hr[BATCH * HID];            // h*r exchange, [b][j]
__device__ unsigned g_bar[4];                     // per-batch-group barrier counters

// bf16-split scratch for tensor-core xproj
__device__ __nv_bfloat16 g_Ah[(size_t)16384 * 512];
__device__ __nv_bfloat16 g_Al[(size_t)16384 * 512];
__device__ __nv_bfloat16 g_Wh[(size_t)3 * 512 * 512];
__device__ __nv_bfloat16 g_Wl[(size_t)3 * 512 * 512];

__global__ void reset_kernel() {
    if (threadIdx.x < 4) g_bar[threadIdx.x] = 0u;
}

// ============================================================================
// fp32 -> (bf16 hi, bf16 lo) conversion kernels
// ============================================================================
__device__ __forceinline__ void split_bf16(float v, __nv_bfloat16& hi, __nv_bfloat16& lo) {
    hi = __float2bfloat16(v);
    lo = __float2bfloat16(v - __bfloat162float(hi));
}

// A matrix: 16384 x 512.  amode 0: from x[b][t][k] (m = t*32+b). amode 1: from g_Hseq (row-major).
__global__ __launch_bounds__(256) void convA_kernel(const float* __restrict__ x, int amode) {
    size_t idx = ((size_t)blockIdx.x * 256 + threadIdx.x) * 4;
    int m = (int)(idx >> 9);
    int k = (int)(idx & 511);
    const float* src = amode ? (g_Hseq + idx)
                             : (x + ((size_t)(m & 31) * 512 + (m >> 5)) * 512 + k);
    float4 v = *(const float4*)src;
    __nv_bfloat16 h0, h1, h2, h3, l0, l1, l2, l3;
    split_bf16(v.x, h0, l0); split_bf16(v.y, h1, l1);
    split_bf16(v.z, h2, l2); split_bf16(v.w, h3, l3);
    ((__nv_bfloat162*)(g_Ah + idx))[0] = __nv_bfloat162(h0, h1);
    ((__nv_bfloat162*)(g_Ah + idx))[1] = __nv_bfloat162(h2, h3);
    ((__nv_bfloat162*)(g_Al + idx))[0] = __nv_bfloat162(l0, l1);
    ((__nv_bfloat162*)(g_Al + idx))[1] = __nv_bfloat162(l2, l3);
}

// W x-halves: g (0=u,1=r,2=o) x 512 j x 512 k  (source row stride 1024)
__global__ __launch_bounds__(256) void convW_kernel(
    const float* __restrict__ Wr, const float* __restrict__ Wu, const float* __restrict__ Wo) {
    size_t idx = ((size_t)blockIdx.x * 256 + threadIdx.x) * 4;   // over 3*512*512
    int g = (int)(idx >> 18);
    int r = (int)(idx & 262143);
    int j = r >> 9, k = r & 511;
    const float* W = (g == 0) ? Wu : (g == 1) ? Wr : Wo;
    float4 v = *(const float4*)(W + (size_t)j * 1024 + k);
    __nv_bfloat16 h0, h1, h2, h3, l0, l1, l2, l3;
    split_bf16(v.x, h0, l0); split_bf16(v.y, h1, l1);
    split_bf16(v.z, h2, l2); split_bf16(v.w, h3, l3);
    ((__nv_bfloat162*)(g_Wh + idx))[0] = __nv_bfloat162(h0, h1);
    ((__nv_bfloat162*)(g_Wh + idx))[1] = __nv_bfloat162(h2, h3);
    ((__nv_bfloat162*)(g_Wl + idx))[0] = __nv_bfloat162(l0, l1);
    ((__nv_bfloat162*)(g_Wl + idx))[1] = __nv_bfloat162(l2, l3);
}

// ============================================================================
// Tensor-core xproj:  g_XP[m][n] = A[m][:] . W[n][:] + b[n]
// bf16-split: AhWh + AhWl + AlWh, fp32 accumulate.
// BM=128, BN=64, BK=32, 256 threads = 8 warps (4m x 2n), warp tile 32x32.
// ============================================================================
__device__ __forceinline__ void ldsm_x4(unsigned& r0, unsigned& r1, unsigned& r2, unsigned& r3,
                                        const __nv_bfloat16* p) {
    unsigned a = (unsigned)__cvta_generic_to_shared(p);
    asm volatile("ldmatrix.sync.aligned.m8n8.x4.shared.b16 {%0,%1,%2,%3}, [%4];"
                 : "=r"(r0), "=r"(r1), "=r"(r2), "=r"(r3) : "r"(a));
}

__device__ __forceinline__ void mma_bf16(float* c, const unsigned* a, const unsigned* b) {
    asm volatile("mma.sync.aligned.m16n8k16.row.col.f32.bf16.bf16.f32 "
                 "{%0,%1,%2,%3}, {%4,%5,%6,%7}, {%8,%9}, {%0,%1,%2,%3};"
                 : "+f"(c[0]), "+f"(c[1]), "+f"(c[2]), "+f"(c[3])
                 : "r"(a[0]), "r"(a[1]), "r"(a[2]), "r"(a[3]), "r"(b[0]), "r"(b[1]));
}

#define SM_PITCH 40   // 32 + 8 bf16 pad (16B) -> ldmatrix conflict-free

__global__ __launch_bounds__(256) void xproj_mma_kernel(
    const float* __restrict__ br, const float* __restrict__ bu, const float* __restrict__ bo) {
    __shared__ __nv_bfloat16 Ah_s[128][SM_PITCH];
    __shared__ __nv_bfloat16 Al_s[128][SM_PITCH];
    __shared__ __nv_bfloat16 Wh_s[64][SM_PITCH];
    __shared__ __nv_bfloat16 Wl_s[64][SM_PITCH];

    int tid = threadIdx.x;
    int m0 = blockIdx.x * 128;
    int n0 = blockIdx.y * 64;
    int g = n0 >> 9, j0 = n0 & 511;
    const float* bv = (g == 0) ? bu : (g == 1) ? br : bo;

    int w = tid >> 5, lane = tid & 31;
    int wm = w >> 1, wn = w & 1;

    float acc[2][4][4];
#pragma unroll
    for (int mf = 0; mf < 2; mf++)
#pragma unroll
        for (int nf = 0; nf < 4; nf++)
#pragma unroll
            for (int i = 0; i < 4; i++) acc[mf][nf][i] = 0.f;

    for (int k0 = 0; k0 < 512; k0 += 32) {
        // ---- load tiles (A: 128x32 x2 splits, W: 64x32 x2) ----
#pragma unroll
        for (int q = 0; q < 2; q++) {
            int u = q * 256 + tid;
            int row = u >> 2, c8 = (u & 3) * 8;
            size_t go = (size_t)(m0 + row) * 512 + k0 + c8;
            *(uint4*)&Ah_s[row][c8] = *(const uint4*)(g_Ah + go);
            *(uint4*)&Al_s[row][c8] = *(const uint4*)(g_Al + go);
        }
        {
            int row = tid >> 2, c8 = (tid & 3) * 8;
            size_t go = ((size_t)g * 512 + j0 + row) * 512 + k0 + c8;
            *(uint4*)&Wh_s[row][c8] = *(const uint4*)(g_Wh + go);
            *(uint4*)&Wl_s[row][c8] = *(const uint4*)(g_Wl + go);
        }
        __syncthreads();

#pragma unroll
        for (int k16 = 0; k16 < 32; k16 += 16) {
            unsigned ah[2][4], al[2][4], bh[4][2], bl[4][2];
            int arow = wm * 32 + (lane & 15);
            int acol = k16 + (lane >> 4) * 8;
#pragma unroll
            for (int mf = 0; mf < 2; mf++) {
                ldsm_x4(ah[mf][0], ah[mf][1], ah[mf][2], ah[mf][3], &Ah_s[arow + mf * 16][acol]);
                ldsm_x4(al[mf][0], al[mf][1], al[mf][2], al[mf][3], &Al_s[arow + mf * 16][acol]);
            }
            int brow_ = ((lane & 16) >> 1) + (lane & 7);
            int bcol = k16 + ((lane >> 3) & 1) * 8;
#pragma unroll
            for (int nh = 0; nh < 2; nh++) {
                int rr = wn * 32 + nh * 16 + brow_;
                ldsm_x4(bh[nh * 2][0], bh[nh * 2][1], bh[nh * 2 + 1][0], bh[nh * 2 + 1][1],
                        &Wh_s[rr][bcol]);
                ldsm_x4(bl[nh * 2][0], bl[nh * 2][1], bl[nh * 2 + 1][0], bl[nh * 2 + 1][1],
                        &Wl_s[rr][bcol]);
            }
#pragma unroll
            for (int mf = 0; mf < 2; mf++)
#pragma unroll
                for (int nf = 0; nf < 4; nf++) {
                    mma_bf16(acc[mf][nf], ah[mf], bh[nf]);
                    mma_bf16(acc[mf][nf], ah[mf], bl[nf]);
                    mma_bf16(acc[mf][nf], al[mf], bh[nf]);
                }
        }
        __syncthreads();
    }

    // ---- epilogue: bias + store ----
#pragma unroll
    for (int nf = 0; nf < 4; nf++) {
        int jc = j0 + wn * 32 + nf * 8 + (lane & 3) * 2;
        float b0 = __ldg(bv + jc), b1 = __ldg(bv + jc + 1);
        int ncol = n0 + wn * 32 + nf * 8 + (lane & 3) * 2;
#pragma unroll
        for (int mf = 0; mf < 2; mf++) {
            int r0 = m0 + wm * 32 + mf * 16 + (lane >> 2);
            float2 v0 = make_float2(acc[mf][nf][0] + b0, acc[mf][nf][1] + b1);
            float2 v1 = make_float2(acc[mf][nf][2] + b0, acc[mf][nf][3] + b1);
            *(float2*)(g_XP + (size_t)r0 * 1536 + ncol) = v0;
            *(float2*)(g_XP + (size_t)(r0 + 8) * 1536 + ncol) = v1;
        }
    }
}

// ============================================================================
// Persistent scan kernel. 128 CTAs = 32 column-groups (16 j each) x 4 batch-
// groups (8 b each). Wh slices resident in SMEM all 512 steps. Two release/
// acquire grid barriers per step, scoped to 32-CTA batch groups.
// ============================================================================

__device__ __forceinline__ void bg_barrier(int bg, unsigned target) {
    __syncthreads();
    if (threadIdx.x == 0) {
        unsigned old;
        asm volatile("atom.release.gpu.global.add.u32 %0, [%1], 1;"
                     : "=r"(old) : "l"(&g_bar[bg]) : "memory");
        unsigned v;
        do {
            asm volatile("ld.acquire.gpu.global.u32 %0, [%1];"
                         : "=r"(v) : "l"(&g_bar[bg]) : "memory");
        } while (v < target);
    }
    __syncthreads();
}

__device__ __forceinline__ float4 ldvol4(const float* p) {
    float4 v;
    asm volatile("ld.volatile.global.v4.f32 {%0,%1,%2,%3}, [%4];"
                 : "=f"(v.x), "=f"(v.y), "=f"(v.z), "=f"(v.w)
                 : "l"(p) : "memory");
    return v;
}

// SMEM layout (floats): Wu_s[16*512] @0, Wr_s @8192, Wo_s @16384,
// h_s[8][516] @24576, hr_s[8][516] @28704, red[4352] @32832, U_s[16*8] @37184
#define SCAN_SMEM_FLOATS 37312
#define SCAN_SMEM_BYTES  (SCAN_SMEM_FLOATS * 4)

__global__ __launch_bounds__(256, 1) void scan_kernel(
    int layer,
    const float* __restrict__ Wr_l, const float* __restrict__ Wu_l,
    const float* __restrict__ Wo_l,
    float* __restrict__ dout)
{
    extern __shared__ float sm[];
    float* h_s  = sm + 24576;   // [8][516]
    float* hr_s = sm + 28704;   // [8][516]
    float* red  = sm + 32832;   // max(256*17, 128*33) = 4352
    float* U_s  = sm + 37184;   // [16][8]: jl*8 + b

    int tid = threadIdx.x;
    int cg = blockIdx.x >> 2;   // 0..31 column group (j in [cg*16, cg*16+16))
    int bg = blockIdx.x & 3;    // 0..3  batch group  (b in [bg*8,  bg*8+8))

    // Load recurrent-weight slices W_g[j][512:1024] -> SMEM (coalesced float4)
    {
        const float* srcs[3] = { Wu_l, Wr_l, Wo_l };
#pragma unroll
        for (int g = 0; g < 3; g++) {
            const float* src = srcs[g];
            float* dst = sm + g * 8192;
            for (int it = 0; it < 8; it++) {
                int word = (it * 256 + tid) * 4;
                int jl = word >> 9, k = word & 511;
                float4 v = *(const float4*)(src + (size_t)(cg * 16 + jl) * 1024 + 512 + k);
                *(float4*)(dst + jl * 512 + k) = v;
            }
        }
    }
    // zero own slice of h0
    if (tid < 128) {
        int b = tid >> 4, jl = tid & 15;
        g_hbuf[0][(bg * 8 + b) * 512 + cg * 16 + jl] = 0.f;
    }
    unsigned gen = 0;
    bg_barrier(bg, (++gen) * 32);

    int w = tid >> 5, lane = tid & 31;
    int ks1 = lane & 15, th = lane >> 4;
    int jt2 = w >> 1, bt2 = w & 1, ks2 = lane;

    const float* Wp1 = (w < 4) ? (sm + (w * 4) * 512)
                               : (sm + 8192 + (w * 4 - 16) * 512);
    const float* Wp2 = sm + 16384 + (jt2 * 4) * 512;

    int cur = 0;
    for (int t = 0; t < 512; t++) {
        // ---- stage h (own 8 batches, full 512 cols) into SMEM ----
#pragma unroll
        for (int q = 0; q < 4; q++) {
            int f = (q * 256 + tid) * 4;
            int bl = f >> 9, k = f & 511;
            float4 v = ldvol4(&g_hbuf[cur][(bg * 8 + bl) * 512 + k]);
            *(float4*)(h_s + bl * 516 + k) = v;
        }
        __syncthreads();

        // ---- phase 1: u and r gates (32 (j,g)-cols x 8 b per CTA) ----
        float acc[4][4];
#pragma unroll
        for (int a = 0; a < 4; a++)
#pragma unroll
            for (int b = 0; b < 4; b++) acc[a][b] = 0.f;
        {
            const float* hp = h_s + (th * 4) * 516;
#pragma unroll 4
            for (int i = 0; i < 32; i++) {
                int k = ks1 + 16 * i;
                float h0 = hp[k], h1 = hp[516 + k], h2 = hp[1032 + k], h3 = hp[1548 + k];
#pragma unroll
                for (int ji = 0; ji < 4; ji++) {
                    float wv = Wp1[ji * 512 + k];
                    acc[ji][0] = fmaf(wv, h0, acc[ji][0]);
                    acc[ji][1] = fmaf(wv, h1, acc[ji][1]);
                    acc[ji][2] = fmaf(wv, h2, acc[ji][2]);
                    acc[ji][3] = fmaf(wv, h3, acc[ji][3]);
                }
            }
        }
#pragma unroll
        for (int ji = 0; ji < 4; ji++)
#pragma unroll
            for (int bi = 0; bi < 4; bi++)
                red[((w * 4 + ji) * 8 + th * 4 + bi) * 17 + ks1] = acc[ji][bi];
        __syncthreads();
        {
            int o = tid, jg = o >> 3, b = o & 7;
            float s = 0.f;
#pragma unroll
            for (int kk = 0; kk < 16; kk++) s += red[o * 17 + kk];
            size_t m = (size_t)t * 32 + bg * 8 + b;
            if (jg < 16) {                      // update gate u
                float pre = s + g_XP[m * 1536 + cg * 16 + jg];
                U_s[jg * 8 + b] = 1.f / (1.f + expf(-pre));
            } else {                            // reset gate r -> publish h*r
                int j = cg * 16 + (jg - 16);
                float pre = s + g_XP[m * 1536 + 512 + j];
                float r = 1.f / (1.f + expf(-pre));
                g_hr[(bg * 8 + b) * 512 + j] = h_s[b * 516 + j] * r;
            }
        }
        bg_barrier(bg, (++gen) * 32);

        // ---- phase 2: o gate + h update (16 j x 8 b per CTA) ----
#pragma unroll
        for (int q = 0; q < 4; q++) {
            int f = (q * 256 + tid) * 4;
            int bl = f >> 9, k = f & 511;
            float4 v = ldvol4(&g_hr[(bg * 8 + bl) * 512 + k]);
            *(float4*)(hr_s + bl * 516 + k) = v;
        }
        __syncthreads();
        float a2[4][4];
#pragma unroll
        for (int a = 0; a < 4; a++)
#pragma unroll
            for (int b = 0; b < 4; b++) a2[a][b] = 0.f;
        {
            const float* hp = hr_s + (bt2 * 4) * 516;
#pragma unroll 4
            for (int i = 0; i < 16; i++) {
                int k = ks2 + 32 * i;
                float h0 = hp[k], h1 = hp[516 + k], h2 = hp[1032 + k], h3 = hp[1548 + k];
#pragma unroll
                for (int ji = 0; ji < 4; ji++) {
                    float wv = Wp2[ji * 512 + k];
                    a2[ji][0] = fmaf(wv, h0, a2[ji][0]);
                    a2[ji][1] = fmaf(wv, h1, a2[ji][1]);
                    a2[ji][2] = fmaf(wv, h2, a2[ji][2]);
                    a2[ji][3] = fmaf(wv, h3, a2[ji][3]);
                }
            }
        }
#pragma unroll
        for (int ji = 0; ji < 4; ji++)
#pragma unroll
            for (int bi = 0; bi < 4; bi++)
                red[((jt2 * 4 + ji) * 8 + bt2 * 4 + bi) * 33 + ks2] = a2[ji][bi];
        __syncthreads();
        if (tid < 128) {
            int o = tid, jl = o >> 3, b = o & 7;
            float s = 0.f;
#pragma unroll
            for (int kk = 0; kk < 32; kk++) s += red[o * 33 + kk];
            int j = cg * 16 + jl;
            int bglob = bg * 8 + b;
            size_t m = (size_t)t * 32 + bglob;
            float pre = s + g_XP[m * 1536 + 1024 + j];
            float ov = tanhf(pre);
            float u = U_s[jl * 8 + b];
            float hold = h_s[b * 516 + j];
            float hn = fmaf(u, ov - hold, hold);      // h*(1-u) + o*u
            g_hbuf[cur ^ 1][bglob * 512 + j] = hn;
            if (layer == 0) g_Hseq[m * 512 + j] = hn;
            if (t == 511) dout[layer * 16384 + bglob * 512 + j] = hn;
        }
        bg_barrier(bg, (++gen) * 32);
        cur ^= 1;
    }
}

// ============================================================================
extern "C" void kernel_launch(void* const* d_in, const int* in_sizes, int n_in,
                              void* d_out, int out_size)
{
    (void)in_sizes; (void)n_in; (void)out_size;
    const float* x  = (const float*)d_in[0];
    const float* Wr = (const float*)d_in[1];
    const float* br = (const float*)d_in[2];
    const float* Wu = (const float*)d_in[3];
    const float* bu = (const float*)d_in[4];
    const float* Wo = (const float*)d_in[5];
    const float* bo = (const float*)d_in[6];
    float* out = (float*)d_out;

    cudaFuncSetAttribute(scan_kernel,
                         cudaFuncAttributeMaxDynamicSharedMemorySize,
                         SCAN_SMEM_BYTES);

    for (int l = 0; l < 2; l++) {
        size_t woff = (size_t)l * 512 * 1024;
        reset_kernel<<<1, 32>>>();
        convA_kernel<<<8192, 256>>>(x, l);
        convW_kernel<<<768, 256>>>(Wr + woff, Wu + woff, Wo + woff);
        xproj_mma_kernel<<<dim3(128, 24), 256>>>(br + l * 512, bu + l * 512, bo + l * 512);
        scan_kernel<<<128, 256, SCAN_SMEM_BYTES>>>(l,
                                                   Wr + woff, Wu + woff, Wo + woff,
                                                   out);
    }
}